// round 1
// baseline (speedup 1.0000x reference)
#include <cuda_runtime.h>

#define Bsz 4
#define Cc  128
#define Hh  64
#define Ww  64
#define Kk  7
#define NHh 8
#define DHh 16
#define PADk 3
#define HW  (Hh*Ww)        // 4096
#define CHW (Cc*HW)        // 524288

// scratch for projections (allocation-free rule: device globals)
__device__ float g_q[Bsz*CHW];
__device__ float g_k[Bsz*CHW];
__device__ float g_v[Bsz*CHW];

// ---------------------------------------------------------------------------
// Kernel 1: fused QKV 1x1-conv GEMM.  out[m,n] = sum_c W[m,c]*x[c,n] + bias[m]
// M=128 per projection, N = B*H*W = 16384, Kdim=128.
// blockIdx.y selects projection (0=q,1=k,2=v). BM=BN=128, BK=16, 256 thr, 8x8/thr.
// ---------------------------------------------------------------------------
__global__ __launch_bounds__(256) void qkv_gemm(
    const float* __restrict__ x,
    const float* __restrict__ wq, const float* __restrict__ bq,
    const float* __restrict__ wk, const float* __restrict__ bk,
    const float* __restrict__ wv, const float* __restrict__ bv)
{
    __shared__ float Ws[128][17];   // [m][cc], padded
    __shared__ float Bs[16][128];   // [cc][n]

    const float* W; const float* bias; float* out;
    if (blockIdx.y == 0)      { W = wq; bias = bq; out = g_q; }
    else if (blockIdx.y == 1) { W = wk; bias = bk; out = g_k; }
    else                      { W = wv; bias = bv; out = g_v; }

    const int tid = threadIdx.x;
    const int tx = tid & 15, ty = tid >> 4;
    const int n0 = blockIdx.x * 128;
    const int b  = n0 >> 12;
    const int hw0 = n0 & 4095;
    const float* xb = x + b * CHW + hw0;

    float acc[8][8];
#pragma unroll
    for (int i = 0; i < 8; i++)
#pragma unroll
        for (int j = 0; j < 8; j++) acc[i][j] = 0.f;

    for (int c0 = 0; c0 < 128; c0 += 16) {
        // W tile: coalesced along c
#pragma unroll
        for (int t = tid; t < 2048; t += 256) {
            int m = t >> 4, cc = t & 15;
            Ws[m][cc] = W[m * 128 + c0 + cc];
        }
        // X tile: coalesced along n
#pragma unroll
        for (int t = tid; t < 2048; t += 256) {
            int cc = t >> 7, n = t & 127;
            Bs[cc][n] = xb[(c0 + cc) * HW + n];
        }
        __syncthreads();
#pragma unroll
        for (int kk = 0; kk < 16; kk++) {
            float a[8], bb[8];
#pragma unroll
            for (int i = 0; i < 4; i++) {
                a[i]     = Ws[ty * 4 + i][kk];
                a[4 + i] = Ws[64 + ty * 4 + i][kk];
            }
            float4 b0 = *(const float4*)&Bs[kk][tx * 4];
            float4 b1 = *(const float4*)&Bs[kk][64 + tx * 4];
            bb[0] = b0.x; bb[1] = b0.y; bb[2] = b0.z; bb[3] = b0.w;
            bb[4] = b1.x; bb[5] = b1.y; bb[6] = b1.z; bb[7] = b1.w;
#pragma unroll
            for (int i = 0; i < 8; i++)
#pragma unroll
                for (int j = 0; j < 8; j++)
                    acc[i][j] += a[i] * bb[j];
        }
        __syncthreads();
    }

    float* outp = out + b * CHW + hw0;
#pragma unroll
    for (int i = 0; i < 8; i++) {
        int m = (i < 4) ? (ty * 4 + i) : (64 + ty * 4 + (i - 4));
        float bi = bias[m];
#pragma unroll
        for (int j = 0; j < 8; j++) {
            int n = (j < 4) ? (tx * 4 + j) : (64 + tx * 4 + (j - 4));
            outp[m * HW + n] = acc[i][j] + bi;
        }
    }
}

// ---------------------------------------------------------------------------
// Kernel 2: local attention. One block = 8x32 pixel tile for one (b, head).
// K/V neighborhood tiles in smem laid [d][r][c] (scalar LDS, conflict-free:
// a warp is one 32-wide pixel row -> consecutive addresses).
// Out-of-bounds neighbors use bias (pad(x)=0 -> proj = bias).
// ---------------------------------------------------------------------------
#define TH 8
#define TW 32
#define HLH (TH + Kk - 1)   // 14
#define HLW (TW + Kk - 1)   // 38
#define TILE_ELEMS (DHh * HLH * HLW)   // 8512

__global__ __launch_bounds__(256) void attn_kernel(
    const float* __restrict__ bk, const float* __restrict__ bv,
    const float* __restrict__ pos_h, const float* __restrict__ pos_w,
    float* __restrict__ outp)
{
    extern __shared__ float sm[];
    float* ks = sm;
    float* vs = sm + TILE_ELEMS;

    const int tileIdx = blockIdx.x;       // 16 tiles: 8 tile-rows x 2 tile-cols
    const int tr = tileIdx >> 1, tc = tileIdx & 1;
    const int h0 = tr * TH, w0 = tc * TW;
    const int nh = blockIdx.y, b = blockIdx.z;
    const int tx = threadIdx.x, ty = threadIdx.y;
    const int tid = ty * TW + tx;

    const int cbase = nh * DHh;
    const float* kb = g_k + (size_t)(b * Cc + cbase) * HW;
    const float* vb = g_v + (size_t)(b * Cc + cbase) * HW;

    for (int idx = tid; idx < TILE_ELEMS; idx += 256) {
        int d  = idx / (HLH * HLW);
        int rc = idx - d * (HLH * HLW);
        int r  = rc / HLW, c = rc - r * HLW;
        int gh = h0 - PADk + r, gw = w0 - PADk + c;
        float kvv, vvv;
        if ((unsigned)gh < (unsigned)Hh && (unsigned)gw < (unsigned)Ww) {
            kvv = kb[d * HW + gh * Ww + gw];
            vvv = vb[d * HW + gh * Ww + gw];
        } else {
            kvv = bk[cbase + d];
            vvv = bv[cbase + d];
        }
        ks[idx] = kvv;
        vs[idx] = vvv;
    }
    __syncthreads();

    const int h = h0 + ty, w = w0 + tx;
    const float* qp = g_q + ((size_t)(b * Cc + cbase) * Hh + h) * Ww + w;
    float q[16];
#pragma unroll
    for (int d = 0; d < 16; d++) q[d] = qp[d * HW];

    float ph[7], pw[7];
#pragma unroll
    for (int i = 0; i < 7; i++) {
        ph[i] = pos_h[nh * 7 + i];
        pw[i] = pos_w[nh * 7 + i];
    }

    float logit[49];
#pragma unroll
    for (int i = 0; i < 7; i++) {
#pragma unroll
        for (int j = 0; j < 7; j++) {
            const float* kp = &ks[(ty + i) * HLW + (tx + j)];
            float s = 0.f;
#pragma unroll
            for (int d = 0; d < 16; d++) s += q[d] * kp[d * (HLH * HLW)];
            logit[i * 7 + j] = s + ph[i] + pw[j];
        }
    }

    float m = logit[0];
#pragma unroll
    for (int t = 1; t < 49; t++) m = fmaxf(m, logit[t]);
    float ssum = 0.f;
#pragma unroll
    for (int t = 0; t < 49; t++) {
        float e = __expf(logit[t] - m);
        logit[t] = e;
        ssum += e;
    }
    const float inv = 1.f / ssum;

    float acc[16];
#pragma unroll
    for (int d = 0; d < 16; d++) acc[d] = 0.f;
#pragma unroll
    for (int i = 0; i < 7; i++) {
#pragma unroll
        for (int j = 0; j < 7; j++) {
            float wgt = logit[i * 7 + j];
            const float* vp = &vs[(ty + i) * HLW + (tx + j)];
#pragma unroll
            for (int d = 0; d < 16; d++) acc[d] += wgt * vp[d * (HLH * HLW)];
        }
    }

    float* op = outp + ((size_t)(b * Cc + cbase) * Hh + h) * Ww + w;
#pragma unroll
    for (int d = 0; d < 16; d++) op[d * HW] = acc[d] * inv;
}

// ---------------------------------------------------------------------------
extern "C" void kernel_launch(void* const* d_in, const int* in_sizes, int n_in,
                              void* d_out, int out_size) {
    const float* x  = (const float*)d_in[0];
    const float* wq = (const float*)d_in[1];
    const float* bq = (const float*)d_in[2];
    const float* wk = (const float*)d_in[3];
    const float* bk = (const float*)d_in[4];
    const float* wv = (const float*)d_in[5];
    const float* bv = (const float*)d_in[6];
    const float* ph = (const float*)d_in[7];
    const float* pw = (const float*)d_in[8];
    float* out = (float*)d_out;

    const size_t smem_bytes = 2u * TILE_ELEMS * sizeof(float);  // 68096
    cudaFuncSetAttribute((const void*)attn_kernel,
                         cudaFuncAttributeMaxDynamicSharedMemorySize,
                         (int)smem_bytes);

    qkv_gemm<<<dim3(128, 3), 256>>>(x, wq, bq, wk, bk, wv, bv);
    attn_kernel<<<dim3(16, NHh, Bsz), dim3(TW, TH), smem_bytes>>>(bk, bv, ph, pw, out);
}